// round 6
// baseline (speedup 1.0000x reference)
#include <cuda_runtime.h>

#define Bc   4
#define Hc   512
#define Wc   229
#define Cc   32
#define OUTc 88
#define FRAME_ELEMS (Bc*Hc*OUTc)     /* 180224 */
#define NROW (Bc*Hc)                 /* 2048 */
#define RB   16                      /* rows per block in kernel 2 */
#define OVTP 18                      /* padded transposed-ov stride (even!) */
#define OVT_FLOATS 4124              /* Wc*OVTP=4122, padded to mult of 4 for s_part float4 alignment */
#define NT2  352                     /* k2 threads: 8 rp x 11 og x 4 ks */

__device__ float g_ov[NROW*Wc];       // Σ_k attn_k * nb_k per pixel
__device__ float g_wT[Wc*OUTc];       // folded linear weights, transposed [w][o]

// ---------------------------------------------------------------------------
// fast exp(d), d <= 0 : FMA-pipe exp2 poly + magic-number round
// ---------------------------------------------------------------------------
__device__ __forceinline__ float fexp_neg(float d)
{
    const float L2E   = 1.4426950408889634f;
    const float MAGIC = 12582912.0f;              // 1.5 * 2^23
    float t0 = fmaf(d, L2E, MAGIC);
    float r  = t0 - MAGIC;
    float f  = fmaf(d, L2E, -r);                  // f in [-0.5, 0.5]
    float p = 1.3333558146e-3f;
    p = fmaf(p, f, 9.6181291076e-3f);
    p = fmaf(p, f, 5.5504108665e-2f);
    p = fmaf(p, f, 2.4022650696e-1f);
    p = fmaf(p, f, 6.9314718056e-1f);
    p = fmaf(p, f, 1.0f);
    int ri = __float_as_int(t0) - 0x4B400000;
    ri = ri < -126 ? -126 : ri;
    return p * __int_as_float((ri + 127) << 23);
}

// ---------------------------------------------------------------------------
// K1: per-(b,h)-row softmax + attn + ov. Scalars computed inline per block.
// Blocks 0..87 additionally fold W_lin -> WeffT column (tail work).
// ---------------------------------------------------------------------------
__global__ void k1(const float* __restrict__ spec,
                   const float* __restrict__ Wq,  const float* __restrict__ Wk,
                   const float* __restrict__ Wv,  const float* __restrict__ rel_t,
                   const float* __restrict__ rel_f, const float* __restrict__ W_lin,
                   float* __restrict__ out_attn)
{
    int blk = blockIdx.x;
    int b = blk >> 9, h = blk & 511;
    __shared__ float sh[3][232];
    __shared__ float sh_attn[Wc*9];
    __shared__ float s_scal[7];
    int t = threadIdx.x;

    if (t < 7) {
        if (t == 0) {
            float a = 0.f;
            #pragma unroll
            for (int c = 0; c < Cc; c++) a = fmaf(Wq[c], Wk[c], a);
            s_scal[0] = a;
        } else if (t <= 3) {
            int kt = t - 1; float r = 0.f;
            #pragma unroll
            for (int c = 0; c < 16; c++) r = fmaf(Wq[c], rel_t[c*3 + kt], r);
            s_scal[t] = r;
        } else {
            int kf = t - 4; float r = 0.f;
            #pragma unroll
            for (int c = 0; c < 16; c++) r = fmaf(Wq[16 + c], rel_f[c*3 + kf], r);
            s_scal[t] = r;
        }
    }

    for (int i = t; i < 3*231; i += 256) {
        int row = i / 231, c = i % 231 - 1;
        int gh = h - 1 + row;
        float v = 0.f;
        if (gh >= 0 && gh < Hc && c >= 0 && c < Wc)
            v = spec[(b*Hc + gh)*Wc + c];
        sh[row][i % 231] = v;
    }
    __syncthreads();

    if (t < Wc) {
        const float A = s_scal[0];
        const float Rt[3] = { s_scal[1], s_scal[2], s_scal[3] };
        const float Rf[3] = { s_scal[4], s_scal[5], s_scal[6] };

        float s  = sh[1][t + 1];
        float sA = s * A;
        float nb[9], e[9];
        #pragma unroll
        for (int kt = 0; kt < 3; kt++) {
            float sr = s * Rt[kt];
            #pragma unroll
            for (int kf = 0; kf < 3; kf++) {
                float n = sh[kt][t + kf];
                nb[kt*3 + kf] = n;
                e[kt*3 + kf]  = fmaf(sA, n, fmaf(s, Rf[kf], sr));
            }
        }

        float m = e[0];
        #pragma unroll
        for (int k = 1; k < 9; k++) m = fmaxf(m, e[k]);

        float p[9], sum = 0.f;
        #pragma unroll
        for (int k = 0; k < 9; k++) { p[k] = fexp_neg(e[k] - m); sum += p[k]; }
        float rinv = __fdividef(1.f, sum);

        float ov = 0.f;
        #pragma unroll
        for (int k = 0; k < 9; k++) {
            float a = p[k] * rinv;
            sh_attn[t*9 + k] = a;
            ov = fmaf(a, nb[k], ov);
        }
        g_ov[blk*Wc + t] = ov;
    }
    __syncthreads();

    float* dst = out_attn + blk*(Wc*9);
    for (int i = t; i < Wc*9; i += 256)
        dst[i] = sh_attn[i];

    if (blk < OUTc && t < Wc) {
        const float* base = W_lin + blk*(Cc*Wc) + t;
        float acc = 0.f;
        #pragma unroll
        for (int c = 0; c < Cc; c++)
            acc = fmaf(base[c*Wc], Wv[c], acc);
        g_wT[t*OUTc + blk] = acc;
    }
}

// ---------------------------------------------------------------------------
// K2: frame_pred = sigmoid(ov @ Weff^T + b)
// 128 blocks x 352 threads, 16 rows x 88 outs per block.
// Thread = (rp, og, ks): 2 rows x 8 outs, K split 4 ways (57-58 w each).
// ov transposed in smem [w][16] (pad 18); wv loads are 4-line coalesced.
// ---------------------------------------------------------------------------
__global__ void __launch_bounds__(NT2, 1)
k2(const float* __restrict__ b_lin, float* __restrict__ out_frame)
{
    extern __shared__ float sm[];
    float* s_wT  = sm;                       // [229][88]           20152 floats
    float* s_ovT = sm + Wc*OUTc;             // [229][18] (+2 pad)  4124 floats
    float* s_part= s_ovT + OVT_FLOATS;       // [3][88][16]  (16B-aligned base)
    int t  = threadIdx.x;
    int rb = blockIdx.x * RB;

    {   // Weff^T copy (contiguous float4)
        const float4* src = (const float4*)g_wT;
        float4* dst = (float4*)s_wT;
        for (int i = t; i < (Wc*OUTc)/4; i += NT2) dst[i] = src[i];
    }
    // ov transposed fill: coalesced gmem read, strided smem write
    for (int i = t; i < RB*Wc; i += NT2) {
        int r = i / Wc, w = i - r*Wc;
        s_ovT[w*OVTP + r] = g_ov[(rb + r)*Wc + w];
    }
    __syncthreads();

    int rp = t & 7;                          // row pair 0..7
    int og = (t >> 3) % 11;                  // out octet 0..10
    int ks = t / 88;                         // K-split 0..3

    int w0 = ks * 57 + (ks ? 1 : 0);
    int w1 = (ks + 1) * 57 + 1;              // 58 | 115 | 172 | 229

    const float* wq  = s_wT + og*8;
    const float* ovp = s_ovT + rp*2;

    float4 accA0 = {0,0,0,0}, accB0 = {0,0,0,0};   // row0: outs 0-3, 4-7
    float4 accA1 = {0,0,0,0}, accB1 = {0,0,0,0};   // row1

    int w = w0;
    for (; w + 2 <= w1; w += 2) {
        float4 wa0 = *(const float4*)(wq + (w  )*OUTc);
        float4 wb0 = *(const float4*)(wq + (w  )*OUTc + 4);
        float4 wa1 = *(const float4*)(wq + (w+1)*OUTc);
        float4 wb1 = *(const float4*)(wq + (w+1)*OUTc + 4);
        float2 o0  = *(const float2*)(ovp + (w  )*OVTP);
        float2 o1  = *(const float2*)(ovp + (w+1)*OVTP);

        accA0.x = fmaf(o0.x, wa0.x, accA0.x); accA0.y = fmaf(o0.x, wa0.y, accA0.y);
        accA0.z = fmaf(o0.x, wa0.z, accA0.z); accA0.w = fmaf(o0.x, wa0.w, accA0.w);
        accB0.x = fmaf(o0.x, wb0.x, accB0.x); accB0.y = fmaf(o0.x, wb0.y, accB0.y);
        accB0.z = fmaf(o0.x, wb0.z, accB0.z); accB0.w = fmaf(o0.x, wb0.w, accB0.w);
        accA1.x = fmaf(o0.y, wa0.x, accA1.x); accA1.y = fmaf(o0.y, wa0.y, accA1.y);
        accA1.z = fmaf(o0.y, wa0.z, accA1.z); accA1.w = fmaf(o0.y, wa0.w, accA1.w);
        accB1.x = fmaf(o0.y, wb0.x, accB1.x); accB1.y = fmaf(o0.y, wb0.y, accB1.y);
        accB1.z = fmaf(o0.y, wb0.z, accB1.z); accB1.w = fmaf(o0.y, wb0.w, accB1.w);

        accA0.x = fmaf(o1.x, wa1.x, accA0.x); accA0.y = fmaf(o1.x, wa1.y, accA0.y);
        accA0.z = fmaf(o1.x, wa1.z, accA0.z); accA0.w = fmaf(o1.x, wa1.w, accA0.w);
        accB0.x = fmaf(o1.x, wb1.x, accB0.x); accB0.y = fmaf(o1.x, wb1.y, accB0.y);
        accB0.z = fmaf(o1.x, wb1.z, accB0.z); accB0.w = fmaf(o1.x, wb1.w, accB0.w);
        accA1.x = fmaf(o1.y, wa1.x, accA1.x); accA1.y = fmaf(o1.y, wa1.y, accA1.y);
        accA1.z = fmaf(o1.y, wa1.z, accA1.z); accA1.w = fmaf(o1.y, wa1.w, accA1.w);
        accB1.x = fmaf(o1.y, wb1.x, accB1.x); accB1.y = fmaf(o1.y, wb1.y, accB1.y);
        accB1.z = fmaf(o1.y, wb1.z, accB1.z); accB1.w = fmaf(o1.y, wb1.w, accB1.w);
    }
    for (; w < w1; w++) {
        float4 wa = *(const float4*)(wq + w*OUTc);
        float4 wb = *(const float4*)(wq + w*OUTc + 4);
        float2 o  = *(const float2*)(ovp + w*OVTP);
        accA0.x = fmaf(o.x, wa.x, accA0.x); accA0.y = fmaf(o.x, wa.y, accA0.y);
        accA0.z = fmaf(o.x, wa.z, accA0.z); accA0.w = fmaf(o.x, wa.w, accA0.w);
        accB0.x = fmaf(o.x, wb.x, accB0.x); accB0.y = fmaf(o.x, wb.y, accB0.y);
        accB0.z = fmaf(o.x, wb.z, accB0.z); accB0.w = fmaf(o.x, wb.w, accB0.w);
        accA1.x = fmaf(o.y, wa.x, accA1.x); accA1.y = fmaf(o.y, wa.y, accA1.y);
        accA1.z = fmaf(o.y, wa.z, accA1.z); accA1.w = fmaf(o.y, wa.w, accA1.w);
        accB1.x = fmaf(o.y, wb.x, accB1.x); accB1.y = fmaf(o.y, wb.y, accB1.y);
        accB1.z = fmaf(o.y, wb.z, accB1.z); accB1.w = fmaf(o.y, wb.w, accB1.w);
    }

    if (ks > 0) {                            // publish partials
        float* pp = s_part + ((ks - 1)*88 + (t - ks*88)) * 16;
        *(float4*)(pp     ) = accA0;  *(float4*)(pp +  4) = accB0;
        *(float4*)(pp +  8) = accA1;  *(float4*)(pp + 12) = accB1;
    }
    __syncthreads();

    if (t < 88) {                            // ks==0 threads reduce + epilogue
        #pragma unroll
        for (int s = 0; s < 3; s++) {
            const float* pp = s_part + (s*88 + t) * 16;
            accA0.x += pp[0];  accA0.y += pp[1];  accA0.z += pp[2];  accA0.w += pp[3];
            accB0.x += pp[4];  accB0.y += pp[5];  accB0.z += pp[6];  accB0.w += pp[7];
            accA1.x += pp[8];  accA1.y += pp[9];  accA1.z += pp[10]; accA1.w += pp[11];
            accB1.x += pp[12]; accB1.y += pp[13]; accB1.z += pp[14]; accB1.w += pp[15];
        }

        float4 ba = *(const float4*)&b_lin[og*8];
        float4 bb = *(const float4*)&b_lin[og*8 + 4];
        float4 rA0, rB0, rA1, rB1;
        rA0.x = __fdividef(1.f, 1.f + __expf(-(accA0.x + ba.x)));
        rA0.y = __fdividef(1.f, 1.f + __expf(-(accA0.y + ba.y)));
        rA0.z = __fdividef(1.f, 1.f + __expf(-(accA0.z + ba.z)));
        rA0.w = __fdividef(1.f, 1.f + __expf(-(accA0.w + ba.w)));
        rB0.x = __fdividef(1.f, 1.f + __expf(-(accB0.x + bb.x)));
        rB0.y = __fdividef(1.f, 1.f + __expf(-(accB0.y + bb.y)));
        rB0.z = __fdividef(1.f, 1.f + __expf(-(accB0.z + bb.z)));
        rB0.w = __fdividef(1.f, 1.f + __expf(-(accB0.w + bb.w)));
        rA1.x = __fdividef(1.f, 1.f + __expf(-(accA1.x + ba.x)));
        rA1.y = __fdividef(1.f, 1.f + __expf(-(accA1.y + ba.y)));
        rA1.z = __fdividef(1.f, 1.f + __expf(-(accA1.z + ba.z)));
        rA1.w = __fdividef(1.f, 1.f + __expf(-(accA1.w + ba.w)));
        rB1.x = __fdividef(1.f, 1.f + __expf(-(accB1.x + bb.x)));
        rB1.y = __fdividef(1.f, 1.f + __expf(-(accB1.y + bb.y)));
        rB1.z = __fdividef(1.f, 1.f + __expf(-(accB1.z + bb.z)));
        rB1.w = __fdividef(1.f, 1.f + __expf(-(accB1.w + bb.w)));

        int row0 = rb + rp*2;
        float* d0 = out_frame + row0*OUTc + og*8;
        float* d1 = d0 + OUTc;
        *(float4*)(d0)     = rA0;  *(float4*)(d0 + 4) = rB0;
        *(float4*)(d1)     = rA1;  *(float4*)(d1 + 4) = rB1;
    }
}

// ---------------------------------------------------------------------------
extern "C" void kernel_launch(void* const* d_in, const int* in_sizes, int n_in,
                              void* d_out, int out_size)
{
    const float* spec  = (const float*)d_in[0];
    const float* Wq    = (const float*)d_in[1];
    const float* Wk    = (const float*)d_in[2];
    const float* Wv    = (const float*)d_in[3];
    const float* rel_t = (const float*)d_in[4];
    const float* rel_f = (const float*)d_in[5];
    const float* W_lin = (const float*)d_in[6];
    const float* b_lin = (const float*)d_in[7];
    float* out = (float*)d_out;

    const int smemC = (Wc*OUTc + OVT_FLOATS + 3*88*16) * (int)sizeof(float); // ~114 KB
    cudaFuncSetAttribute(k2, cudaFuncAttributeMaxDynamicSharedMemorySize, smemC);

    k1<<<NROW, 256>>>(spec, Wq, Wk, Wv, rel_t, rel_f, W_lin, out + FRAME_ELEMS);
    k2<<<NROW/RB, NT2, smemC>>>(b_lin, out);
}

// round 7
// speedup vs baseline: 1.0625x; 1.0625x over previous
#include <cuda_runtime.h>

#define Bc   4
#define Hc   512
#define Wc   229
#define Cc   32
#define OUTc 88
#define WTP  96                      /* padded weight out-stride */
#define FRAME_ELEMS (Bc*Hc*OUTc)     /* 180224 */
#define NROW (Bc*Hc)                 /* 2048 */
#define RB   16                      /* rows per k2 block */
#define OVTP 20                      /* transposed-ov stride: mult4, 4-way bank */
#define PRTP 20                      /* partials stride */

__device__ float g_ov[NROW*Wc];       // Σ_k attn_k * nb_k per pixel
__device__ float g_wT96[Wc*WTP];      // folded weights, transposed [w][o], o-pad 96 (zero-init)

// ---------------------------------------------------------------------------
// fast exp(d), d <= 0 : FMA-pipe exp2 poly + magic-number round
// ---------------------------------------------------------------------------
__device__ __forceinline__ float fexp_neg(float d)
{
    const float L2E   = 1.4426950408889634f;
    const float MAGIC = 12582912.0f;              // 1.5 * 2^23
    float t0 = fmaf(d, L2E, MAGIC);
    float r  = t0 - MAGIC;
    float f  = fmaf(d, L2E, -r);                  // f in [-0.5, 0.5]
    float p = 1.3333558146e-3f;
    p = fmaf(p, f, 9.6181291076e-3f);
    p = fmaf(p, f, 5.5504108665e-2f);
    p = fmaf(p, f, 2.4022650696e-1f);
    p = fmaf(p, f, 6.9314718056e-1f);
    p = fmaf(p, f, 1.0f);
    int ri = __float_as_int(t0) - 0x4B400000;
    ri = ri < -126 ? -126 : ri;
    return p * __int_as_float((ri + 127) << 23);
}

// ---------------------------------------------------------------------------
// K1: per-(b,h)-row softmax + attn + ov. Scalars inline; blocks 0..87 fold
// one WeffT column into g_wT96.
// ---------------------------------------------------------------------------
__global__ void k1(const float* __restrict__ spec,
                   const float* __restrict__ Wq,  const float* __restrict__ Wk,
                   const float* __restrict__ Wv,  const float* __restrict__ rel_t,
                   const float* __restrict__ rel_f, const float* __restrict__ W_lin,
                   float* __restrict__ out_attn)
{
    int blk = blockIdx.x;
    int b = blk >> 9, h = blk & 511;
    __shared__ float sh[3][232];
    __shared__ float sh_attn[Wc*9];
    __shared__ float s_scal[7];
    int t = threadIdx.x;

    if (t < 7) {
        if (t == 0) {
            float a = 0.f;
            #pragma unroll
            for (int c = 0; c < Cc; c++) a = fmaf(Wq[c], Wk[c], a);
            s_scal[0] = a;
        } else if (t <= 3) {
            int kt = t - 1; float r = 0.f;
            #pragma unroll
            for (int c = 0; c < 16; c++) r = fmaf(Wq[c], rel_t[c*3 + kt], r);
            s_scal[t] = r;
        } else {
            int kf = t - 4; float r = 0.f;
            #pragma unroll
            for (int c = 0; c < 16; c++) r = fmaf(Wq[16 + c], rel_f[c*3 + kf], r);
            s_scal[t] = r;
        }
    }

    for (int i = t; i < 3*231; i += 256) {
        int row = i / 231, c = i % 231 - 1;
        int gh = h - 1 + row;
        float v = 0.f;
        if (gh >= 0 && gh < Hc && c >= 0 && c < Wc)
            v = spec[(b*Hc + gh)*Wc + c];
        sh[row][i % 231] = v;
    }
    __syncthreads();

    if (t < Wc) {
        const float A = s_scal[0];
        const float Rt[3] = { s_scal[1], s_scal[2], s_scal[3] };
        const float Rf[3] = { s_scal[4], s_scal[5], s_scal[6] };

        float s  = sh[1][t + 1];
        float sA = s * A;
        float nb[9], e[9];
        #pragma unroll
        for (int kt = 0; kt < 3; kt++) {
            float sr = s * Rt[kt];
            #pragma unroll
            for (int kf = 0; kf < 3; kf++) {
                float n = sh[kt][t + kf];
                nb[kt*3 + kf] = n;
                e[kt*3 + kf]  = fmaf(sA, n, fmaf(s, Rf[kf], sr));
            }
        }

        float m = e[0];
        #pragma unroll
        for (int k = 1; k < 9; k++) m = fmaxf(m, e[k]);

        float p[9], sum = 0.f;
        #pragma unroll
        for (int k = 0; k < 9; k++) { p[k] = fexp_neg(e[k] - m); sum += p[k]; }
        float rinv = __fdividef(1.f, sum);

        float ov = 0.f;
        #pragma unroll
        for (int k = 0; k < 9; k++) {
            float a = p[k] * rinv;
            sh_attn[t*9 + k] = a;
            ov = fmaf(a, nb[k], ov);
        }
        g_ov[blk*Wc + t] = ov;
    }
    __syncthreads();

    float* dst = out_attn + blk*(Wc*9);
    for (int i = t; i < Wc*9; i += 256)
        dst[i] = sh_attn[i];

    if (blk < OUTc && t < Wc) {
        const float* base = W_lin + blk*(Cc*Wc) + t;
        float acc = 0.f;
        #pragma unroll
        for (int c = 0; c < Cc; c++)
            acc = fmaf(base[c*Wc], Wv[c], acc);
        g_wT96[t*WTP + blk] = acc;
    }
}

// ---------------------------------------------------------------------------
// K2: frame_pred = sigmoid(ov @ Weff^T + b)
// grid (3 outTiles, 128 rowTiles) x 256 threads. Block tile: 16 rows x 32 outs.
// warp = K-chunk (8 chunks of ~29 w); lane = rq(4 row-quads) x og(8 out-quads).
// Per w: 1 float4 wv + 1 float4 ov -> 16 FMA.  ~64KB smem -> 3 blocks/SM.
// ---------------------------------------------------------------------------
__global__ void __launch_bounds__(256, 3)
k2(const float* __restrict__ b_lin, float* __restrict__ out_frame)
{
    extern __shared__ float sm[];
    float* s_w   = sm;                       // [229][32]      7328 floats
    float* s_ovT = sm + Wc*32;               // [229][20]      4580 floats
    float* s_prt = s_ovT + Wc*OVTP;          // [7][32][20]    4480 floats
    int t  = threadIdx.x;
    int ot = blockIdx.x;                     // out tile 0..2
    int rb = blockIdx.y * RB;                // row base

    // weight tile: g_wT96[w][ot*32 + j], float4 both sides
    for (int f = t; f < (Wc*32)/4; f += 256) {
        int w = f >> 3, jq = f & 7;
        ((float4*)s_w)[f] = *(const float4*)&g_wT96[w*WTP + ot*32 + jq*4];
    }
    // ov transposed fill: coalesced gmem read, 4-way-conflict smem write
    for (int i = t; i < RB*Wc; i += 256) {
        int r = i / Wc, w = i - r*Wc;
        s_ovT[w*OVTP + r] = g_ov[(rb + r)*Wc + w];
    }
    __syncthreads();

    int lane = t & 31;
    int ks   = t >> 5;                       // warp id = K chunk 0..7
    int rq   = lane & 3;                     // row quad 0..3
    int og   = lane >> 2;                    // out quad 0..7

    int w0 = (ks * Wc) >> 3;
    int w1 = ((ks + 1) * Wc) >> 3;

    const float* wq = s_w   + og*4;
    const float* op = s_ovT + rq*4;

    float4 acc0 = {0,0,0,0}, acc1 = {0,0,0,0};
    float4 acc2 = {0,0,0,0}, acc3 = {0,0,0,0};

    int w = w0;
    for (; w + 2 <= w1; w += 2) {
        float4 wv0 = *(const float4*)(wq + (w  )*32);
        float4 ov0 = *(const float4*)(op + (w  )*OVTP);
        float4 wv1 = *(const float4*)(wq + (w+1)*32);
        float4 ov1 = *(const float4*)(op + (w+1)*OVTP);

        acc0.x = fmaf(ov0.x, wv0.x, acc0.x); acc0.y = fmaf(ov0.x, wv0.y, acc0.y);
        acc0.z = fmaf(ov0.x, wv0.z, acc0.z); acc0.w = fmaf(ov0.x, wv0.w, acc0.w);
        acc1.x = fmaf(ov0.y, wv0.x, acc1.x); acc1.y = fmaf(ov0.y, wv0.y, acc1.y);
        acc1.z = fmaf(ov0.y, wv0.z, acc1.z); acc1.w = fmaf(ov0.y, wv0.w, acc1.w);
        acc2.x = fmaf(ov0.z, wv0.x, acc2.x); acc2.y = fmaf(ov0.z, wv0.y, acc2.y);
        acc2.z = fmaf(ov0.z, wv0.z, acc2.z); acc2.w = fmaf(ov0.z, wv0.w, acc2.w);
        acc3.x = fmaf(ov0.w, wv0.x, acc3.x); acc3.y = fmaf(ov0.w, wv0.y, acc3.y);
        acc3.z = fmaf(ov0.w, wv0.z, acc3.z); acc3.w = fmaf(ov0.w, wv0.w, acc3.w);

        acc0.x = fmaf(ov1.x, wv1.x, acc0.x); acc0.y = fmaf(ov1.x, wv1.y, acc0.y);
        acc0.z = fmaf(ov1.x, wv1.z, acc0.z); acc0.w = fmaf(ov1.x, wv1.w, acc0.w);
        acc1.x = fmaf(ov1.y, wv1.x, acc1.x); acc1.y = fmaf(ov1.y, wv1.y, acc1.y);
        acc1.z = fmaf(ov1.y, wv1.z, acc1.z); acc1.w = fmaf(ov1.y, wv1.w, acc1.w);
        acc2.x = fmaf(ov1.z, wv1.x, acc2.x); acc2.y = fmaf(ov1.z, wv1.y, acc2.y);
        acc2.z = fmaf(ov1.z, wv1.z, acc2.z); acc2.w = fmaf(ov1.z, wv1.w, acc2.w);
        acc3.x = fmaf(ov1.w, wv1.x, acc3.x); acc3.y = fmaf(ov1.w, wv1.y, acc3.y);
        acc3.z = fmaf(ov1.w, wv1.z, acc3.z); acc3.w = fmaf(ov1.w, wv1.w, acc3.w);
    }
    for (; w < w1; w++) {
        float4 wv = *(const float4*)(wq + w*32);
        float4 ov = *(const float4*)(op + w*OVTP);
        acc0.x = fmaf(ov.x, wv.x, acc0.x); acc0.y = fmaf(ov.x, wv.y, acc0.y);
        acc0.z = fmaf(ov.x, wv.z, acc0.z); acc0.w = fmaf(ov.x, wv.w, acc0.w);
        acc1.x = fmaf(ov.y, wv.x, acc1.x); acc1.y = fmaf(ov.y, wv.y, acc1.y);
        acc1.z = fmaf(ov.y, wv.z, acc1.z); acc1.w = fmaf(ov.y, wv.w, acc1.w);
        acc2.x = fmaf(ov.z, wv.x, acc2.x); acc2.y = fmaf(ov.z, wv.y, acc2.y);
        acc2.z = fmaf(ov.z, wv.z, acc2.z); acc2.w = fmaf(ov.z, wv.w, acc2.w);
        acc3.x = fmaf(ov.w, wv.x, acc3.x); acc3.y = fmaf(ov.w, wv.y, acc3.y);
        acc3.z = fmaf(ov.w, wv.z, acc3.z); acc3.w = fmaf(ov.w, wv.w, acc3.w);
    }

    if (ks > 0) {                            // publish partials (stride 20)
        float* pp = s_prt + ((ks - 1)*32 + lane)*PRTP;
        *(float4*)(pp     ) = acc0;  *(float4*)(pp +  4) = acc1;
        *(float4*)(pp +  8) = acc2;  *(float4*)(pp + 12) = acc3;
    }
    __syncthreads();

    if (t < 32) {                            // warp 0 reduces + epilogue
        #pragma unroll
        for (int s = 0; s < 7; s++) {
            const float* pp = s_prt + (s*32 + lane)*PRTP;
            float4 p0 = *(const float4*)(pp);
            float4 p1 = *(const float4*)(pp + 4);
            float4 p2 = *(const float4*)(pp + 8);
            float4 p3 = *(const float4*)(pp + 12);
            acc0.x += p0.x; acc0.y += p0.y; acc0.z += p0.z; acc0.w += p0.w;
            acc1.x += p1.x; acc1.y += p1.y; acc1.z += p1.z; acc1.w += p1.w;
            acc2.x += p2.x; acc2.y += p2.y; acc2.z += p2.z; acc2.w += p2.w;
            acc3.x += p3.x; acc3.y += p3.y; acc3.z += p3.z; acc3.w += p3.w;
        }

        int o = ot*32 + og*4;
        if (o < OUTc) {                      // pad outs (88..95) skipped
            float4 bb = *(const float4*)&b_lin[o];
            float4 accs[4] = {acc0, acc1, acc2, acc3};
            #pragma unroll
            for (int i = 0; i < 4; i++) {
                float4 rr;
                rr.x = __fdividef(1.f, 1.f + __expf(-(accs[i].x + bb.x)));
                rr.y = __fdividef(1.f, 1.f + __expf(-(accs[i].y + bb.y)));
                rr.z = __fdividef(1.f, 1.f + __expf(-(accs[i].z + bb.z)));
                rr.w = __fdividef(1.f, 1.f + __expf(-(accs[i].w + bb.w)));
                int row = rb + rq*4 + i;
                *(float4*)&out_frame[row*OUTc + o] = rr;
            }
        }
    }
}

// ---------------------------------------------------------------------------
extern "C" void kernel_launch(void* const* d_in, const int* in_sizes, int n_in,
                              void* d_out, int out_size)
{
    const float* spec  = (const float*)d_in[0];
    const float* Wq    = (const float*)d_in[1];
    const float* Wk    = (const float*)d_in[2];
    const float* Wv    = (const float*)d_in[3];
    const float* rel_t = (const float*)d_in[4];
    const float* rel_f = (const float*)d_in[5];
    const float* W_lin = (const float*)d_in[6];
    const float* b_lin = (const float*)d_in[7];
    float* out = (float*)d_out;

    const int smemC = (Wc*32 + Wc*OVTP + 7*32*PRTP) * (int)sizeof(float); // 65552 B
    cudaFuncSetAttribute(k2, cudaFuncAttributeMaxDynamicSharedMemorySize, smemC);

    k1<<<NROW, 256>>>(spec, Wq, Wk, Wv, rel_t, rel_f, W_lin, out + FRAME_ELEMS);
    dim3 g2(3, NROW/RB);
    k2<<<g2, 256, smemC>>>(b_lin, out);
}